// round 4
// baseline (speedup 1.0000x reference)
#include <cuda_runtime.h>
#include <cuda_bf16.h>
#include <math.h>
#include <stdint.h>

#define DTC 0.001
#define Pdim 1024
#define Hdim 256
#define Ldim 16384
#define Ktot 2048      // 2*P
#define Ntot 32768     // 2*L
#define NKC  32        // K chunks of 64
#define NSTAGE 3
#define STAGE_BYTES 65536

// ---------------------------------------------------------------------------
// Device-global scratch (allocation-free rule)
// ---------------------------------------------------------------------------
__device__ __align__(16) float2  g_ab[Pdim];     // fp32 A_bar
__device__ __align__(16) float2  g_cf[Pdim];     // (A_bar-1)/Ac
__device__ __align__(16) double2 g_lg[Pdim];     // log(A_bar) fp64
// A matrices [kc(32)][m(256)][kk(64)] bf16  (1 MB each)
__device__ __align__(128) __nv_bfloat16 g_Ahi[(size_t)32 * 256 * 64];
__device__ __align__(128) __nv_bfloat16 g_Alo[(size_t)32 * 256 * 64];
// B matrices [kc(32)][n(32768)][kk(64)] bf16 (128 MB each)
__device__ __align__(128) __nv_bfloat16 g_Bhi[(size_t)32 * 32768 * 64];
__device__ __align__(128) __nv_bfloat16 g_Blo[(size_t)32 * 32768 * 64];

// ---------------------------------------------------------------------------
// helpers
// ---------------------------------------------------------------------------
__device__ __forceinline__ uint32_t s2u(const void* p) {
    uint32_t a;
    asm("{ .reg .u64 t; cvta.to.shared.u64 t, %1; cvt.u32.u64 %0, t; }"
        : "=r"(a) : "l"(p));
    return a;
}

__device__ __forceinline__ unsigned pack_bf(float lo, float hi) {
    unsigned r;
    asm("{\n\t.reg .b16 a, b;\n\tcvt.rn.bf16.f32 a, %1;\n\tcvt.rn.bf16.f32 b, %2;\n\t"
        "mov.b32 %0, {a, b};\n\t}" : "=r"(r) : "f"(lo), "f"(hi));
    return r;
}

__device__ __forceinline__ void cpa(uint32_t dst, const void* src) {
    asm volatile("cp.async.cg.shared.global [%0], [%1], 16;"
                 :: "r"(dst), "l"(src) : "memory");
}

__device__ __forceinline__ void ldm4(uint32_t* r, uint32_t a) {
    asm volatile("ldmatrix.sync.aligned.m8n8.x4.shared.b16 {%0,%1,%2,%3}, [%4];"
                 : "=r"(r[0]), "=r"(r[1]), "=r"(r[2]), "=r"(r[3]) : "r"(a));
}

__device__ __forceinline__ void mma16816(float* d, const uint32_t* a,
                                         uint32_t b0, uint32_t b1) {
    asm volatile(
        "mma.sync.aligned.m16n8k16.row.col.f32.bf16.bf16.f32 "
        "{%0,%1,%2,%3}, {%4,%5,%6,%7}, {%8,%9}, {%0,%1,%2,%3};"
        : "+f"(d[0]), "+f"(d[1]), "+f"(d[2]), "+f"(d[3])
        : "r"(a[0]), "r"(a[1]), "r"(a[2]), "r"(a[3]), "r"(b0), "r"(b1));
}

// ---------------------------------------------------------------------------
// k_pre: per-p constants (fp64 transcendentals once per p)
// ---------------------------------------------------------------------------
__global__ void k_pre(const float* __restrict__ A) {
    int p = blockIdx.x * blockDim.x + threadIdx.x;
    if (p >= Pdim) return;
    float ar = A[2 * p], ai = A[2 * p + 1];
    double e = exp((double)ar * DTC), th = (double)ai * DTC;
    float abr = (float)(e * cos(th));
    float abi = (float)(e * sin(th));
    float nr = abr - 1.0f, ni = abi;
    float den = ar * ar + ai * ai;
    g_ab[p] = make_float2(abr, abi);
    g_cf[p] = make_float2((nr * ar + ni * ai) / den, (ni * ar - nr * ai) / den);
    g_lg[p] = make_double2(0.5 * log((double)abr * abr + (double)abi * abi),
                           atan2((double)abi, (double)abr));
}

// ---------------------------------------------------------------------------
// k_setupA: W[h,p] = C[h,p]*coef[p]*B[p,h]; packed-real, split bf16 hi/lo.
// Layout [kc][m=h][kk=64], A[h][2p]=Wr, A[h][2p+1]=Wi.
// ---------------------------------------------------------------------------
__global__ void k_setupA(const float* __restrict__ B, const float* __restrict__ C) {
    int idx = blockIdx.x * 256 + threadIdx.x;     // over P*H
    int p = idx & (Pdim - 1), h = idx >> 10;
    float2 cf = g_cf[p];
    float br = B[(p * Hdim + h) * 2], bi = B[(p * Hdim + h) * 2 + 1];
    float bbr = cf.x * br - cf.y * bi;
    float bbi = cf.x * bi + cf.y * br;
    float cr = C[(h * Pdim + p) * 2], ci = C[(h * Pdim + p) * 2 + 1];
    float wr = cr * bbr - ci * bbi;
    float wi = cr * bbi + ci * bbr;
    float wrh = __bfloat162float(__float2bfloat16_rn(wr));
    float wih = __bfloat162float(__float2bfloat16_rn(wi));
    size_t o = ((size_t)(p >> 5) * 256 + h) * 32 + (p & 31);
    ((unsigned*)g_Ahi)[o] = pack_bf(wr, wi);
    ((unsigned*)g_Alo)[o] = pack_bf(wr - wrh, wi - wih);
}

// ---------------------------------------------------------------------------
// k_genB: V[p,l] via fp32 recurrence (seeded fp64 every 128 l), written as
// packed-real bf16 hi/lo B matrices. Lanes own consecutive p -> coalesced.
// ---------------------------------------------------------------------------
__global__ void k_genB() {
    int wid = blockIdx.x * 8 + (threadIdx.x >> 5);   // 4096 warps
    int lane = threadIdx.x & 31;
    int pg = wid & 31, seg = wid >> 5;               // seg 0..127
    int p = pg * 32 + lane;

    float2 ab = g_ab[p];
    double2 lg = g_lg[p];
    int l0 = seg * 128;
    double m = exp(lg.x * (double)l0), a = lg.y * (double)l0;
    float vr = (float)(m * cos(a));
    float vi = (float)(m * sin(a));

    unsigned* bh = (unsigned*)g_Bhi;
    unsigned* bl = (unsigned*)g_Blo;
    size_t rowbase = (size_t)pg * 32768 * 32 + lane;  // u32 units

    #pragma unroll 4
    for (int t = 0; t < 128; t++) {
        int l = l0 + t;
        float vrh = __bfloat162float(__float2bfloat16_rn(vr));
        float vih = __bfloat162float(__float2bfloat16_rn(vi));
        size_t o0 = rowbase + (size_t)(2 * l) * 32;
        bh[o0]      = pack_bf(vr, -vi);          // row n=2l   : (Vr, -Vi)
        bh[o0 + 32] = pack_bf(vi, vr);           // row n=2l+1 : (Vi,  Vr)
        bl[o0]      = pack_bf(vr - vrh, -(vi - vih));
        bl[o0 + 32] = pack_bf(vi - vih, vr - vrh);
        float nvr = vr * ab.x - vi * ab.y;
        float nvi = vr * ab.y + vi * ab.x;
        vr = nvr; vi = nvi;
    }
}

// ---------------------------------------------------------------------------
// k_gemm: HMMA mma.sync bf16, CTA tile 128m x 128n, 512 thr (16 warps 4x4,
// warp tile 32x32). 3-stage cp.async pipeline (192 KB smem), ONE barrier per
// chunk, fragment double-buffering across ks-steps.
// 3 products per chunk: Ahi*Bhi + Ahi*Blo + Alo*Bhi into fp32 acc.
// Stage layout: [Ahi 16K][Alo 16K][Bhi 16K][Blo 16K] = 64K per stage.
// ---------------------------------------------------------------------------
__global__ __launch_bounds__(512, 1) void k_gemm(float* __restrict__ out) {
    extern __shared__ char smp[];
    const int tid  = threadIdx.x;
    const int lane = tid & 31;
    const int wid  = tid >> 5;
    const int wm   = wid >> 2;            // 0..3
    const int wn   = wid & 3;             // 0..3
    const int m0   = blockIdx.x * 128;
    const int n0   = blockIdx.y * 128;
    const uint32_t sb = s2u(smp);

    float acc[2][4][4];
    #pragma unroll
    for (int i = 0; i < 2; i++)
        #pragma unroll
        for (int j = 0; j < 4; j++)
            #pragma unroll
            for (int t = 0; t < 4; t++) acc[i][j][t] = 0.0f;

    // cp.async staging mapping: thread covers 2 (row,col) slots per plane.
    const int crow = tid >> 3;            // 0..63 (+64 on second iter)
    const int ccol = tid & 7;             // 16B column

    auto issue = [&](int kc, int s) {
        uint32_t st = sb + s * STAGE_BYTES;
        #pragma unroll
        for (int i = 0; i < 2; i++) {
            int row = crow + 64 * i;
            uint32_t d = st + row * 128 + ((ccol ^ (row & 7)) << 4);
            size_t oA = ((size_t)kc * 256 + m0 + row) * 64 + ccol * 8;
            cpa(d,         g_Ahi + oA);
            cpa(d + 16384, g_Alo + oA);
            size_t oB = ((size_t)kc * 32768 + n0 + row) * 64 + ccol * 8;
            cpa(d + 32768, g_Bhi + oB);
            cpa(d + 49152, g_Blo + oB);
        }
        asm volatile("cp.async.commit_group;" ::: "memory");
    };

    // ldmatrix per-lane row bases
    const int r15 = lane & 15, h16 = lane >> 4;
    const int rA0 = wm * 32 + r15, rA1 = rA0 + 16;
    const int rB0 = wn * 32 + r15, rB1 = rB0 + 16;

    // fragment double buffers
    uint32_t fah[2][8], fal[2][8], fbh[2][8], fbl[2][8];

    issue(0, 0);
    issue(1, 1);

    for (int k = 0; k < NKC; k++) {
        const int s = k % NSTAGE;
        if (k + 2 < NKC)
            asm volatile("cp.async.wait_group 1;" ::: "memory");
        else
            asm volatile("cp.async.wait_group 0;" ::: "memory");
        __syncthreads();
        if (k + 2 < NKC) issue(k + 2, (k + 2) % NSTAGE);

        const uint32_t sA = sb + s * STAGE_BYTES;
        const uint32_t sB = sA + 32768;

        // load_frags for ks-step into buffer buf
        auto load_frags = [&](int buf, int ks) {
            const int cc = 2 * ks + h16;
            uint32_t oA0 = rA0 * 128 + ((cc ^ (rA0 & 7)) << 4);
            uint32_t oA1 = rA1 * 128 + ((cc ^ (rA1 & 7)) << 4);
            uint32_t oB0 = rB0 * 128 + ((cc ^ (rB0 & 7)) << 4);
            uint32_t oB1 = rB1 * 128 + ((cc ^ (rB1 & 7)) << 4);
            ldm4(&fah[buf][0], sA + oA0);
            ldm4(&fah[buf][4], sA + oA1);
            ldm4(&fal[buf][0], sA + 16384 + oA0);
            ldm4(&fal[buf][4], sA + 16384 + oA1);
            ldm4(&fbh[buf][0], sB + oB0);
            ldm4(&fbh[buf][4], sB + oB1);
            ldm4(&fbl[buf][0], sB + 16384 + oB0);
            ldm4(&fbl[buf][4], sB + 16384 + oB1);
        };

        load_frags(0, 0);

        #pragma unroll
        for (int ks = 0; ks < 4; ks++) {
            const int b = ks & 1;
            if (ks < 3) load_frags(b ^ 1, ks + 1);

            const uint32_t* a0 = &fah[b][0];
            const uint32_t* a1 = &fah[b][4];
            const uint32_t* l0p = &fal[b][0];
            const uint32_t* l1p = &fal[b][4];
            const uint32_t* b0h = &fbh[b][0];
            const uint32_t* b1h = &fbh[b][4];
            const uint32_t* b0l = &fbl[b][0];
            const uint32_t* b1l = &fbl[b][4];

            // hi*hi
            mma16816(acc[0][0], a0, b0h[0], b0h[2]);
            mma16816(acc[0][1], a0, b0h[1], b0h[3]);
            mma16816(acc[0][2], a0, b1h[0], b1h[2]);
            mma16816(acc[0][3], a0, b1h[1], b1h[3]);
            mma16816(acc[1][0], a1, b0h[0], b0h[2]);
            mma16816(acc[1][1], a1, b0h[1], b0h[3]);
            mma16816(acc[1][2], a1, b1h[0], b1h[2]);
            mma16816(acc[1][3], a1, b1h[1], b1h[3]);
            // hi*lo
            mma16816(acc[0][0], a0, b0l[0], b0l[2]);
            mma16816(acc[0][1], a0, b0l[1], b0l[3]);
            mma16816(acc[0][2], a0, b1l[0], b1l[2]);
            mma16816(acc[0][3], a0, b1l[1], b1l[3]);
            mma16816(acc[1][0], a1, b0l[0], b0l[2]);
            mma16816(acc[1][1], a1, b0l[1], b0l[3]);
            mma16816(acc[1][2], a1, b1l[0], b1l[2]);
            mma16816(acc[1][3], a1, b1l[1], b1l[3]);
            // lo*hi
            mma16816(acc[0][0], l0p, b0h[0], b0h[2]);
            mma16816(acc[0][1], l0p, b0h[1], b0h[3]);
            mma16816(acc[0][2], l0p, b1h[0], b1h[2]);
            mma16816(acc[0][3], l0p, b1h[1], b1h[3]);
            mma16816(acc[1][0], l1p, b0h[0], b0h[2]);
            mma16816(acc[1][1], l1p, b0h[1], b0h[3]);
            mma16816(acc[1][2], l1p, b1h[0], b1h[2]);
            mma16816(acc[1][3], l1p, b1h[1], b1h[3]);
        }
        // no trailing barrier: with 3 stages the slot issued at k+2 was
        // computed at k-1, which the iter-(k) barrier already ordered.
    }

    // Epilogue
    const int mrow = lane >> 2, ncol = (lane & 3) * 2;
    #pragma unroll
    for (int im = 0; im < 2; im++) {
        int m = m0 + wm * 32 + im * 16 + mrow;
        #pragma unroll
        for (int jn = 0; jn < 4; jn++) {
            int n = n0 + wn * 32 + jn * 8 + ncol;
            float* p = out + (size_t)m * Ntot + n;
            *(float2*)p = make_float2(acc[im][jn][0], acc[im][jn][1]);
            *(float2*)(p + (size_t)8 * Ntot) = make_float2(acc[im][jn][2], acc[im][jn][3]);
        }
    }
}

// ---------------------------------------------------------------------------
extern "C" void kernel_launch(void* const* d_in, const int* in_sizes, int n_in,
                              void* d_out, int out_size) {
    const float* A = (const float*)d_in[0];
    const float* B = (const float*)d_in[1];
    const float* C = (const float*)d_in[2];
    float* out = (float*)d_out;

    cudaFuncSetAttribute(k_gemm, cudaFuncAttributeMaxDynamicSharedMemorySize, 196608);

    k_pre<<<4, 256>>>(A);
    k_setupA<<<1024, 256>>>(B, C);
    k_genB<<<512, 256>>>();
    k_gemm<<<dim3(2, 256), 512, 196608>>>(out);
}

// round 5
// speedup vs baseline: 1.2191x; 1.2191x over previous
#include <cuda_runtime.h>
#include <cuda_bf16.h>
#include <math.h>
#include <stdint.h>

#define DTC 0.001
#define Pdim 1024
#define Hdim 256
#define Ldim 16384
#define NKC  16        // K chunks of 64 (K = P = 1024 per GEMM now)
#define NSTAGE 3
#define STAGE_BYTES 65536

// ---------------------------------------------------------------------------
// Device-global scratch (allocation-free rule)
// ---------------------------------------------------------------------------
__device__ __align__(16) float2  g_ab[Pdim];     // fp32 A_bar
__device__ __align__(16) float2  g_cf[Pdim];     // (A_bar-1)/Ac
__device__ __align__(16) double2 g_lg[Pdim];     // log(A_bar) fp64
// A planes [variant: r_hi, r_lo, i_hi, i_lo, s_hi, s_lo][kc(16)][m=h(256)][kk(64)]
__device__ __align__(128) __nv_bfloat16 g_A[6][(size_t)16 * 256 * 64];
// B planes same variant order, [kc(16)][n=l(16384)][kk(64)]  (32 MB each)
__device__ __align__(128) __nv_bfloat16 g_B[6][(size_t)16 * 16384 * 64];
// Partial GEMM outputs Gr, Gi, Gm  (16 MB each)
__device__ __align__(128) float g_G[3][(size_t)256 * 16384];

// ---------------------------------------------------------------------------
// helpers
// ---------------------------------------------------------------------------
__device__ __forceinline__ uint32_t s2u(const void* p) {
    uint32_t a;
    asm("{ .reg .u64 t; cvta.to.shared.u64 t, %1; cvt.u32.u64 %0, t; }"
        : "=r"(a) : "l"(p));
    return a;
}

__device__ __forceinline__ void cpa(uint32_t dst, const void* src) {
    asm volatile("cp.async.cg.shared.global [%0], [%1], 16;"
                 :: "r"(dst), "l"(src) : "memory");
}

__device__ __forceinline__ void ldm4(uint32_t* r, uint32_t a) {
    asm volatile("ldmatrix.sync.aligned.m8n8.x4.shared.b16 {%0,%1,%2,%3}, [%4];"
                 : "=r"(r[0]), "=r"(r[1]), "=r"(r[2]), "=r"(r[3]) : "r"(a));
}

__device__ __forceinline__ void mma16816(float* d, const uint32_t* a,
                                         uint32_t b0, uint32_t b1) {
    asm volatile(
        "mma.sync.aligned.m16n8k16.row.col.f32.bf16.bf16.f32 "
        "{%0,%1,%2,%3}, {%4,%5,%6,%7}, {%8,%9}, {%0,%1,%2,%3};"
        : "+f"(d[0]), "+f"(d[1]), "+f"(d[2]), "+f"(d[3])
        : "r"(a[0]), "r"(a[1]), "r"(a[2]), "r"(a[3]), "r"(b0), "r"(b1));
}

// ---------------------------------------------------------------------------
// k_pre: per-p constants (fp64 transcendentals once per p)
// ---------------------------------------------------------------------------
__global__ void k_pre(const float* __restrict__ A) {
    int p = blockIdx.x * blockDim.x + threadIdx.x;
    if (p >= Pdim) return;
    float ar = A[2 * p], ai = A[2 * p + 1];
    double e = exp((double)ar * DTC), th = (double)ai * DTC;
    float abr = (float)(e * cos(th));
    float abi = (float)(e * sin(th));
    float nr = abr - 1.0f, ni = abi;
    float den = ar * ar + ai * ai;
    g_ab[p] = make_float2(abr, abi);
    g_cf[p] = make_float2((nr * ar + ni * ai) / den, (ni * ar - nr * ai) / den);
    g_lg[p] = make_double2(0.5 * log((double)abr * abr + (double)abi * abi),
                           atan2((double)abi, (double)abr));
}

// ---------------------------------------------------------------------------
// k_setupA: W[h,p] = C[h,p]*coef[p]*B[p,h]; 3 variants (Wr, Wi, Wr+Wi) with
// bf16 hi/lo split. Layout [kc][m=h][kk=64], element (h, p).
// ---------------------------------------------------------------------------
__global__ void k_setupA(const float* __restrict__ B, const float* __restrict__ C) {
    int idx = blockIdx.x * 256 + threadIdx.x;     // over P*H
    int p = idx & (Pdim - 1), h = idx >> 10;
    float2 cf = g_cf[p];
    float br = B[(p * Hdim + h) * 2], bi = B[(p * Hdim + h) * 2 + 1];
    float bbr = cf.x * br - cf.y * bi;
    float bbi = cf.x * bi + cf.y * br;
    float cr = C[(h * Pdim + p) * 2], ci = C[(h * Pdim + p) * 2 + 1];
    float wr = cr * bbr - ci * bbi;
    float wi = cr * bbi + ci * bbr;
    float ws = wr + wi;

    size_t o = ((size_t)(p >> 6) * 256 + h) * 64 + (p & 63);
    __nv_bfloat16 hr = __float2bfloat16_rn(wr);
    __nv_bfloat16 hi = __float2bfloat16_rn(wi);
    __nv_bfloat16 hs = __float2bfloat16_rn(ws);
    g_A[0][o] = hr; g_A[1][o] = __float2bfloat16_rn(wr - __bfloat162float(hr));
    g_A[2][o] = hi; g_A[3][o] = __float2bfloat16_rn(wi - __bfloat162float(hi));
    g_A[4][o] = hs; g_A[5][o] = __float2bfloat16_rn(ws - __bfloat162float(hs));
}

// ---------------------------------------------------------------------------
// k_genB: V[p,l] via fp32 recurrence (seeded fp64 every 128 l); writes 3
// variants (Vr, Vi, Vr+Vi) hi/lo. Lanes own consecutive p -> coalesced-ish.
// ---------------------------------------------------------------------------
__global__ void k_genB() {
    int wid = blockIdx.x * 8 + (threadIdx.x >> 5);   // 4096 warps
    int lane = threadIdx.x & 31;
    int pg = wid & 31, seg = wid >> 5;               // seg 0..127
    int p = pg * 32 + lane;

    float2 ab = g_ab[p];
    double2 lg = g_lg[p];
    int l0 = seg * 128;
    double m = exp(lg.x * (double)l0), a = lg.y * (double)l0;
    float vr = (float)(m * cos(a));
    float vi = (float)(m * sin(a));

    const size_t kcbase = (size_t)(p >> 6) * 16384;
    const int kk = p & 63;

    #pragma unroll 4
    for (int t = 0; t < 128; t++) {
        int l = l0 + t;
        float vs = vr + vi;
        __nv_bfloat16 hr = __float2bfloat16_rn(vr);
        __nv_bfloat16 hi = __float2bfloat16_rn(vi);
        __nv_bfloat16 hs = __float2bfloat16_rn(vs);
        size_t o = (kcbase + l) * 64 + kk;
        g_B[0][o] = hr; g_B[1][o] = __float2bfloat16_rn(vr - __bfloat162float(hr));
        g_B[2][o] = hi; g_B[3][o] = __float2bfloat16_rn(vi - __bfloat162float(hi));
        g_B[4][o] = hs; g_B[5][o] = __float2bfloat16_rn(vs - __bfloat162float(hs));
        float nvr = vr * ab.x - vi * ab.y;
        float nvi = vr * ab.y + vi * ab.x;
        vr = nvr; vi = nvi;
    }
}

// ---------------------------------------------------------------------------
// k_gemm: z-batched 3 real GEMMs (Gr, Gi, Gm), each M=256 N=16384 K=1024.
// HMMA mma.sync bf16, CTA tile 128x128, 512 thr (16 warps 4x4, warp 32x32),
// 3-stage cp.async pipeline, hi/lo split: 3 products per chunk.
// Stage layout: [Ahi 16K][Alo 16K][Bhi 16K][Blo 16K].
// ---------------------------------------------------------------------------
__global__ __launch_bounds__(512, 1) void k_gemm() {
    extern __shared__ char smp[];
    const int tid  = threadIdx.x;
    const int lane = tid & 31;
    const int wid  = tid >> 5;
    const int wm   = wid >> 2;            // 0..3
    const int wn   = wid & 3;             // 0..3
    const int m0   = blockIdx.x * 128;
    const int n0   = blockIdx.y * 128;
    const int z    = blockIdx.z;          // 0=r, 1=i, 2=s
    const uint32_t sb = s2u(smp);

    const __nv_bfloat16* Agh = g_A[2 * z];
    const __nv_bfloat16* Agl = g_A[2 * z + 1];
    const __nv_bfloat16* Bgh = g_B[2 * z];
    const __nv_bfloat16* Bgl = g_B[2 * z + 1];

    float acc[2][4][4];
    #pragma unroll
    for (int i = 0; i < 2; i++)
        #pragma unroll
        for (int j = 0; j < 4; j++)
            #pragma unroll
            for (int t = 0; t < 4; t++) acc[i][j][t] = 0.0f;

    const int crow = tid >> 3;            // 0..63 (+64 second iter)
    const int ccol = tid & 7;             // 16B column

    auto issue = [&](int kc, int s) {
        uint32_t st = sb + s * STAGE_BYTES;
        #pragma unroll
        for (int i = 0; i < 2; i++) {
            int row = crow + 64 * i;
            uint32_t d = st + row * 128 + ((ccol ^ (row & 7)) << 4);
            size_t oA = ((size_t)kc * 256 + m0 + row) * 64 + ccol * 8;
            cpa(d,         Agh + oA);
            cpa(d + 16384, Agl + oA);
            size_t oB = ((size_t)kc * 16384 + n0 + row) * 64 + ccol * 8;
            cpa(d + 32768, Bgh + oB);
            cpa(d + 49152, Bgl + oB);
        }
        asm volatile("cp.async.commit_group;" ::: "memory");
    };

    const int r15 = lane & 15, h16 = lane >> 4;
    const int rA0 = wm * 32 + r15, rA1 = rA0 + 16;
    const int rB0 = wn * 32 + r15, rB1 = rB0 + 16;

    issue(0, 0);
    issue(1, 1);

    for (int k = 0; k < NKC; k++) {
        const int s = k % NSTAGE;
        if (k + 2 < NKC)
            asm volatile("cp.async.wait_group 1;" ::: "memory");
        else
            asm volatile("cp.async.wait_group 0;" ::: "memory");
        __syncthreads();
        if (k + 2 < NKC) issue(k + 2, (k + 2) % NSTAGE);

        const uint32_t sA = sb + s * STAGE_BYTES;
        const uint32_t sB = sA + 32768;

        #pragma unroll
        for (int ks = 0; ks < 4; ks++) {
            const int cc = 2 * ks + h16;
            uint32_t a0[4], a1[4], al0[4], al1[4];
            uint32_t bh0[4], bh1[4], bl0[4], bl1[4];
            uint32_t oA0 = rA0 * 128 + ((cc ^ (rA0 & 7)) << 4);
            uint32_t oA1 = rA1 * 128 + ((cc ^ (rA1 & 7)) << 4);
            uint32_t oB0 = rB0 * 128 + ((cc ^ (rB0 & 7)) << 4);
            uint32_t oB1 = rB1 * 128 + ((cc ^ (rB1 & 7)) << 4);

            ldm4(a0,  sA + oA0);
            ldm4(a1,  sA + oA1);
            ldm4(al0, sA + 16384 + oA0);
            ldm4(al1, sA + 16384 + oA1);
            ldm4(bh0, sB + oB0);
            ldm4(bh1, sB + oB1);
            ldm4(bl0, sB + 16384 + oB0);
            ldm4(bl1, sB + 16384 + oB1);

            // hi*hi
            mma16816(acc[0][0], a0, bh0[0], bh0[2]);
            mma16816(acc[0][1], a0, bh0[1], bh0[3]);
            mma16816(acc[0][2], a0, bh1[0], bh1[2]);
            mma16816(acc[0][3], a0, bh1[1], bh1[3]);
            mma16816(acc[1][0], a1, bh0[0], bh0[2]);
            mma16816(acc[1][1], a1, bh0[1], bh0[3]);
            mma16816(acc[1][2], a1, bh1[0], bh1[2]);
            mma16816(acc[1][3], a1, bh1[1], bh1[3]);
            // hi*lo
            mma16816(acc[0][0], a0, bl0[0], bl0[2]);
            mma16816(acc[0][1], a0, bl0[1], bl0[3]);
            mma16816(acc[0][2], a0, bl1[0], bl1[2]);
            mma16816(acc[0][3], a0, bl1[1], bl1[3]);
            mma16816(acc[1][0], a1, bl0[0], bl0[2]);
            mma16816(acc[1][1], a1, bl0[1], bl0[3]);
            mma16816(acc[1][2], a1, bl1[0], bl1[2]);
            mma16816(acc[1][3], a1, bl1[1], bl1[3]);
            // lo*hi
            mma16816(acc[0][0], al0, bh0[0], bh0[2]);
            mma16816(acc[0][1], al0, bh0[1], bh0[3]);
            mma16816(acc[0][2], al0, bh1[0], bh1[2]);
            mma16816(acc[0][3], al0, bh1[1], bh1[3]);
            mma16816(acc[1][0], al1, bh0[0], bh0[2]);
            mma16816(acc[1][1], al1, bh0[1], bh0[3]);
            mma16816(acc[1][2], al1, bh1[0], bh1[2]);
            mma16816(acc[1][3], al1, bh1[1], bh1[3]);
        }
    }

    // Epilogue -> fp32 partial plane
    float* G = g_G[z];
    const int mrow = lane >> 2, ncol = (lane & 3) * 2;
    #pragma unroll
    for (int im = 0; im < 2; im++) {
        int m = m0 + wm * 32 + im * 16 + mrow;
        #pragma unroll
        for (int jn = 0; jn < 4; jn++) {
            int n = n0 + wn * 32 + jn * 8 + ncol;
            float* p = G + (size_t)m * Ldim + n;
            *(float2*)p = make_float2(acc[im][jn][0], acc[im][jn][1]);
            *(float2*)(p + (size_t)8 * Ldim) = make_float2(acc[im][jn][2], acc[im][jn][3]);
        }
    }
}

// ---------------------------------------------------------------------------
// k_comb: out[h][l] = (Gr-Gi, Gm-Gr-Gi), vectorized float4.
// ---------------------------------------------------------------------------
__global__ void k_comb(float4* __restrict__ out) {
    size_t idx = (size_t)blockIdx.x * 256 + threadIdx.x;   // over H*L/4
    const float4* Gr = (const float4*)g_G[0];
    const float4* Gi = (const float4*)g_G[1];
    const float4* Gm = (const float4*)g_G[2];
    float4 r = Gr[idx], i = Gi[idx], m = Gm[idx];
    out[2 * idx] = make_float4(r.x - i.x, m.x - r.x - i.x,
                               r.y - i.y, m.y - r.y - i.y);
    out[2 * idx + 1] = make_float4(r.z - i.z, m.z - r.z - i.z,
                                   r.w - i.w, m.w - r.w - i.w);
}

// ---------------------------------------------------------------------------
extern "C" void kernel_launch(void* const* d_in, const int* in_sizes, int n_in,
                              void* d_out, int out_size) {
    const float* A = (const float*)d_in[0];
    const float* B = (const float*)d_in[1];
    const float* C = (const float*)d_in[2];

    cudaFuncSetAttribute(k_gemm, cudaFuncAttributeMaxDynamicSharedMemorySize, 196608);

    k_pre<<<4, 256>>>(A);
    k_setupA<<<1024, 256>>>(B, C);
    k_genB<<<512, 256>>>();
    k_gemm<<<dim3(2, 128, 3), 512, 196608>>>();
    k_comb<<<4096, 256>>>((float4*)d_out);
}